// round 15
// baseline (speedup 1.0000x reference)
#include <cuda_runtime.h>
#include <cuda_bf16.h>
#include <cstdint>

// Problem shapes (fixed by setup_inputs)
#define B_      4
#define L_      8192
#define BLOCK_  128
#define NB_     (L_ / BLOCK_)          // 64
#define V_      32000
#define D_      1024
#define NT_     (L_ + NB_)             // 8256 new_tokens per batch row

// Output layout (flattened tuple, row-major, float32):
//   [0,        B*NT)                new_tokens      (33024)
//   [OFF_CE,   OFF_CE + B*NB*D)     cat_emb         (262144)
//   [OFF_H,    OFF_H  + B*NB*V)     hist            (8192000)
#define OFF_CE  (B_ * NT_)                         // 33024
#define OFF_H   (OFF_CE + B_ * NB_ * D_)           // 295168

#define NSLICE  (B_ * NB_)                         // 256 hist slices
#define F4SL    (V_ / 4)                           // 8000 float4 per slice
#define F4TOT   (NSLICE * F4SL)                    // 2,048,000 float4
#define NWORDS  (V_ / 32)                          // 1000 bitmap words/slice

#define GRID_   1184                               // 148 SMs x 8 CTAs, 1 wave
#define NTHR    128
#define PER_CTA 1730                               // ceil(F4TOT / GRID_)

__device__ __forceinline__ float4 bits_to_f4(uint32_t w, int r4)
{
    const uint32_t bits = (w >> ((r4 & 7) << 2)) & 0xFu;
    float4 v;
    v.x = (bits & 1u) ? 1.0f : 0.0f;
    v.y = (bits & 2u) ? 1.0f : 0.0f;
    v.z = (bits & 4u) ? 1.0f : 0.0f;
    v.w = (bits & 8u) ? 1.0f : 0.0f;
    return v;
}

// Flat, perfectly SM-balanced decomposition: every CTA drains exactly
// PER_CTA float4 of the hist array (last CTA slightly less). A CTA's range
// spans at most 2 slices; it rebuilds those slices' presence bitmaps from
// the 128 tokens (L2-hit re-reads) and the unique CTA containing a slice's
// start also writes that slice's new_tokens + cat_emb row.
__global__ __launch_bounds__(NTHR)
void chunk_agg_flat(const int* __restrict__ tokens,
                    const float* __restrict__ catW,
                    float* __restrict__ out)
{
    __shared__ uint32_t bm[2][NWORDS];   // 8 KB
    __shared__ int      ov_rel[2][BLOCK_];
    __shared__ int      ov_cnt[2];

    const int bid = blockIdx.x;
    const int tid = threadIdx.x;

    const int f0  = bid * PER_CTA;
    const int f1  = min(f0 + PER_CTA, F4TOT);
    const int sl0 = f0 / F4SL;
    const int sl1 = (f1 - 1) / F4SL;
    const int nsl = sl1 - sl0 + 1;       // 1 or 2

    // ---- zero bitmaps for covered slices
    #pragma unroll
    for (int s = 0; s < 2; ++s)
        if (s < nsl)
            for (int w = tid; w < NWORDS; w += NTHR) bm[s][w] = 0u;
    if (tid < 2) ov_cnt[tid] = 0;
    __syncthreads();

    // ---- per covered slice: set presence bits, side outputs if owner
    int   own_s = -1;
    float4 e0 = make_float4(0.f,0.f,0.f,0.f), e1 = e0;

    for (int s = 0; s < nsl; ++s) {
        const int slice = sl0 + s;
        const int b = slice >> 6;
        const int j = slice & 63;
        const int* __restrict__ blk = tokens + b * L_ + j * BLOCK_;
        const int tok = blk[tid];        // 0..V-1

        const uint32_t mask = 1u << (tok & 31);
        const uint32_t old  = atomicOr(&bm[s][tok >> 5], mask);
        if (old & mask) {                // exact duplicate handling
            const int k = atomicAdd(&ov_cnt[s], 1);
            ov_rel[s][k] = tok;
        }

        // owner: the CTA whose range contains this slice's first float4
        const int sstart = slice * F4SL;
        if (sstart >= f0 && sstart < f1) {
            own_s = s;
            // new_tokens (fire-and-forget)
            out[b * NT_ + NB_ + j * BLOCK_ + tid] = (float)tok;
            if (tid == 0)
                out[b * NT_ + j] = (float)tok;   // tid0 holds blk[0]
            // embed-row prefetch (consumed after the drain)
            const int t0 = blk[0];
            const float4* src =
                reinterpret_cast<const float4*>(catW + (size_t)t0 * D_);
            e0 = src[tid];
            e1 = src[tid + NTHR];
        }
    }

    __syncthreads();

    // ---- drain: equal-sized contiguous store stream per CTA
    float4* __restrict__ h4 = reinterpret_cast<float4*>(out + OFF_H);
    const int base0 = sl0 * F4SL;
    const int bound = base0 + F4SL;      // start of slice sl0+1
    const int nov0  = ov_cnt[0];
    const int nov1  = (nsl > 1) ? ov_cnt[1] : 0;

    if ((nov0 | nov1) == 0) {
        #pragma unroll 4
        for (int i = f0 + tid; i < f1; i += NTHR) {
            const int s  = (i >= bound) ? 1 : 0;
            const int r4 = i - (s ? bound : base0);   // 0..F4SL-1
            h4[i] = bits_to_f4(bm[s][r4 >> 3], r4);
        }
    } else {
        for (int i = f0 + tid; i < f1; i += NTHR) {
            const int s  = (i >= bound) ? 1 : 0;
            const int r4 = i - (s ? bound : base0);
            float4 v = bits_to_f4(bm[s][r4 >> 3], r4);
            const int nov = s ? nov1 : nov0;
            for (int e = 0; e < nov; ++e) {
                const int rel = ov_rel[s][e];
                if ((rel >> 2) == r4) {
                    switch (rel & 3) {
                        case 0: v.x += 1.0f; break;
                        case 1: v.y += 1.0f; break;
                        case 2: v.z += 1.0f; break;
                        default: v.w += 1.0f; break;
                    }
                }
            }
            h4[i] = v;
        }
    }

    // ---- embed-row store (prefetched; latency hidden under the drain)
    if (own_s >= 0) {
        const int slice = sl0 + own_s;
        float4* dst = reinterpret_cast<float4*>(out + OFF_CE + slice * D_);
        dst[tid]        = e0;
        dst[tid + NTHR] = e1;
    }
}

extern "C" void kernel_launch(void* const* d_in, const int* in_sizes, int n_in,
                              void* d_out, int out_size)
{
    const int*   tokens = (const int*)  d_in[0];   // [4, 8192] int32
    const float* catW   = (const float*)d_in[1];   // [32000, 1024] f32
    // d_in[2] (num_embed_W) is a dead lookup in the reference — unused.
    float* out = (float*)d_out;

    chunk_agg_flat<<<GRID_, NTHR>>>(tokens, catW, out);
}